// round 16
// baseline (speedup 1.0000x reference)
#include <cuda_runtime.h>
#include <cuda_bf16.h>
#include <cuda_fp16.h>
typedef unsigned int u32;
#define BB 4
#define SS 2048
#define DD 1024
#define HH 16
#define HD 64
#define MM (BB*SS)
#define BH (BB*HH)
#define SCALE 0.25f
#define LOG2E 1.4426950408889634f

__device__ __half g_xf[MM*DD];
__device__ __half g_Wf[4*DD*DD];
__device__ __half g_Qf[BH*SS*HD];            // Q fp16 (pre-scaled by 0.25*log2e)
__device__ __half g_Kf[BH*SS*HD];
__device__ __half g_Tf[BH*HD*SS];            // V^T fp16 [bh][hd][s]
__device__ u32 g_Pu[134217728];              // 2^s fp16x2, fragment layout [bh][qt][j][w][g][lane]
__device__ __half g_cf[MM*DD];
__device__ float g_l[BH*SS];
__device__ float g_h[MM*DD];

__device__ __forceinline__ u32 sptr(const void* p){u32 a;asm("{.reg .u64 t; cvta.to.shared.u64 t,%1; cvt.u32.u64 %0,t;}":"=r"(a):"l"(p));return a;}
__device__ __forceinline__ u32 swz(int row,int half){return (u32)row*32u+(u32)((half^((row>>2)&1))<<4);}
__device__ __forceinline__ void ldmx4(u32* r,u32 a){asm volatile("ldmatrix.sync.aligned.m8n8.x4.shared.b16 {%0,%1,%2,%3},[%4];":"=r"(r[0]),"=r"(r[1]),"=r"(r[2]),"=r"(r[3]):"r"(a));}
__device__ __forceinline__ void mmah(float* c,const u32* a,u32 b0,u32 b1){
  asm volatile("mma.sync.aligned.m16n8k16.row.col.f32.f16.f16.f32 {%0,%1,%2,%3},{%4,%5,%6,%7},{%8,%9},{%0,%1,%2,%3};"
    :"+f"(c[0]),"+f"(c[1]),"+f"(c[2]),"+f"(c[3]):"r"(a[0]),"r"(a[1]),"r"(a[2]),"r"(a[3]),"r"(b0),"r"(b1));}
__device__ __forceinline__ void cpa(u32 d,const void* s){asm volatile("cp.async.cg.shared.global [%0],[%1],16;"::"r"(d),"l"(s));}
__device__ __forceinline__ u32 pkh(float a,float b){__half2 t=__floats2half2_rn(a,b);return *(u32*)&t;}

__device__ __forceinline__ float bsum(float v){
  __shared__ float sh[8];
  #pragma unroll
  for(int o=16;o;o>>=1) v+=__shfl_xor_sync(~0u,v,o);
  if((threadIdx.x&31)==0) sh[threadIdx.x>>5]=v;
  __syncthreads();
  if(threadIdx.x<32){ v=(threadIdx.x<8)?sh[threadIdx.x]:0.f;
    #pragma unroll
    for(int o=4;o;o>>=1) v+=__shfl_xor_sync(~0u,v,o);
    if(threadIdx.x==0) sh[0]=v; }
  __syncthreads(); float r=sh[0]; __syncthreads(); return r;}

// fp16 single-product GEMM, 32-col k-chunks (2 MMA k-steps per stage): C += A B^T
template<int BM,int BN,int WMW,int WNW,int NSTG>
__device__ void gemm(const __half* __restrict__ A,int lda,
                     const __half* __restrict__ B,int ldb,int kc32,float* c)
{
  constexpr int WTM=BM/WMW, WTN=BN/WNW, MT=WTM/16, NT=WTN/8, NP=NT/2;
  constexpr int APAN=BM*32, BPAN=BN*32;     // bytes per 16-col panel
  constexpr int AB=2*APAN, ST=AB+2*BPAN;    // stage: A(2 panels) + B(2 panels)
  extern __shared__ char sm_[];
  const u32 sm=sptr(sm_);
  const int t=threadIdx.x, lane=t&31, wid=t>>5, wm=wid/WNW, wn=wid%WNW;
  const int gq=lane>>3, r=lane&7;
  u32 offA[MT],offB[NP];
  #pragma unroll
  for(int m=0;m<MT;m++) offA[m]=swz(wm*WTM+m*16+(gq&1)*8+r, gq>>1);
  #pragma unroll
  for(int p=0;p<NP;p++) offB[p]=swz(wn*WTN+p*16+(gq&1)*8+r, gq>>1);
  #pragma unroll
  for(int i=0;i<MT*NT*4;i++) c[i]=0.f;

  auto fill=[&](int ch){
    u32 sb=sm+(ch%NSTG)*ST;
    for(int g=t; g<BM*4; g+=256){
      int row=g>>2, ks=(g>>1)&1, hf=g&1;
      cpa(sb+ks*APAN+swz(row,hf), A+(size_t)row*lda+ch*32+ks*16+hf*8);
    }
    for(int g=t; g<BN*4; g+=256){
      int row=g>>2, ks=(g>>1)&1, hf=g&1;
      cpa(sb+AB+ks*BPAN+swz(row,hf), B+(size_t)row*ldb+ch*32+ks*16+hf*8);
    }
    asm volatile("cp.async.commit_group;":::"memory");
  };
  #pragma unroll
  for(int i=0;i<NSTG-1;i++) if(i<kc32) fill(i);

  for(int ch=0; ch<kc32; ch++){
    int rem=kc32-1-ch; int w=rem<NSTG-2?rem:NSTG-2;
    if(w==0)      asm volatile("cp.async.wait_group 0;":::"memory");
    else          asm volatile("cp.async.wait_group 1;":::"memory");
    __syncthreads();
    if(ch+NSTG-1<kc32) fill(ch+NSTG-1);

    u32 sb=sm+(ch%NSTG)*ST;
    #pragma unroll
    for(int ks=0;ks<2;ks++){
      u32 ah[MT][4], bh[NP][4];
      #pragma unroll
      for(int m=0;m<MT;m++) ldmx4(ah[m],sb+ks*APAN+offA[m]);
      #pragma unroll
      for(int p=0;p<NP;p++) ldmx4(bh[p],sb+AB+ks*BPAN+offB[p]);
      #pragma unroll
      for(int m=0;m<MT;m++)
        #pragma unroll
        for(int n=0;n<NT;n++){
          float* cc=c+(m*NT+n)*4; int p=n>>1,o=n&1;
          mmah(cc,ah[m],bh[p][o],bh[p][2+o]);
        }
    }
  }
}

__global__ __launch_bounds__(256) void k_cvt(const float* __restrict__ x){
  size_t i=((size_t)blockIdx.x*256+threadIdx.x)*8;
  float v[8];
  *(float4*)v=*(const float4*)(x+i); *(float4*)(v+4)=*(const float4*)(x+i+4);
  uint4 H; u32* Hp=&H.x;
  #pragma unroll
  for(int j=0;j<4;j++) Hp[j]=pkh(v[2*j],v[2*j+1]);
  *(uint4*)(g_xf+i)=H;
}

__global__ __launch_bounds__(256) void k_wt(const float* __restrict__ Wq,const float* __restrict__ Wk,
                                            const float* __restrict__ Wv,const float* __restrict__ Wo){
  __shared__ float tl[32][33];
  int z=blockIdx.z; const float* W= z==0?Wq:z==1?Wk:z==2?Wv:Wo;
  int k0=blockIdx.y*32, n0=blockIdx.x*32;
  int tx=threadIdx.x&31, ty=threadIdx.x>>5;
  #pragma unroll
  for(int j=0;j<32;j+=8) tl[ty+j][tx]=W[(size_t)(k0+ty+j)*DD+n0+tx];
  __syncthreads();
  int nl=threadIdx.x>>3, kg=(threadIdx.x&7)*4;
  uint2 H; u32* Hp=&H.x;
  #pragma unroll
  for(int j=0;j<2;j++) Hp[j]=pkh(tl[kg+2*j][nl],tl[kg+2*j+1][nl]);
  *(uint2*)(g_Wf+(size_t)z*DD*DD+(size_t)(n0+nl)*DD+k0+kg)=H;
}

__global__ __launch_bounds__(256) void k_qkv(const float* __restrict__ bq,const float* __restrict__ bk,
                                             const float* __restrict__ bv){
  extern __shared__ char sm_[];
  int z=blockIdx.z, m0=blockIdx.y*128, n0=blockIdx.x*128;
  const float* bias= z==0?bq:z==1?bk:bv;
  float c[64];
  gemm<128,128,2,4,3>(g_xf+(size_t)m0*DD, DD,
                      g_Wf+(size_t)z*DD*DD+(size_t)n0*DD, DD, DD/32, c);
  int lane=threadIdx.x&31, wid=threadIdx.x>>5, wm=wid>>2, wn=wid&3, rb=lane>>2, tg=lane&3;
  if(z<2){
    const float sc = (z==0)?(SCALE*LOG2E):1.0f;
    __half* DF= z==0?g_Qf:g_Kf;
    #pragma unroll
    for(int mt=0;mt<4;mt++)
      #pragma unroll
      for(int nt=0;nt<4;nt++){
        int col=n0+wn*32+nt*8+2*tg;
        float b0=__ldg(bias+col), b1=__ldg(bias+col+1);
        const float* cc=c+(mt*4+nt)*4;
        #pragma unroll
        for(int hf=0;hf<2;hf++){
          int m=m0+wm*64+mt*16+rb+hf*8;
          int b=m>>11, s=m&2047, h=col>>6, hd=col&63;
          *(u32*)(DF+((size_t)(b*HH+h)*SS+s)*HD+hd)=pkh(sc*(cc[2*hf]+b0), sc*(cc[2*hf+1]+b1));
        }
      }
  }else{
    // V: smem-staged transpose -> coalesced 16B stores into g_Tf [bh][hd][s]
    __syncthreads();
    __half* ts=(__half*)sm_;          // [128 cols][136 m] padded (34816 B)
    #pragma unroll
    for(int mt=0;mt<4;mt++)
      #pragma unroll
      for(int nt=0;nt<4;nt++){
        int col=wn*32+nt*8+2*tg;
        float b0=__ldg(bias+n0+col), b1=__ldg(bias+n0+col+1);
        const float* cc=c+(mt*4+nt)*4;
        #pragma unroll
        for(int hf=0;hf<2;hf++){
          int ml=wm*64+mt*16+rb+hf*8;
          ts[col*136+ml]    =__float2half_rn(cc[2*hf]+b0);
          ts[(col+1)*136+ml]=__float2half_rn(cc[2*hf+1]+b1);
        }
      }
    __syncthreads();
    const int b=m0>>11, s0=m0&2047;
    #pragma unroll
    for(int i=0;i<8;i++){
      int lin=threadIdx.x+i*256;
      int row=lin>>4, ch=lin&15;
      uint4 v=*(uint4*)&ts[row*136+ch*8];
      int col=n0+row, h=col>>6, hd=col&63;
      *(uint4*)(g_Tf+((size_t)(b*HH+h)*HD+hd)*SS+s0+ch*8)=v;
    }
  }
}

// Fused flash attention: 128-key stages, two 64-key compute subtiles each.
__global__ __launch_bounds__(256,2) void k_flash(){
  extern __shared__ char sm_[];
  const u32 sm=sptr(sm_);
  const int bh=blockIdx.y, qt=blockIdx.x, m0=qt*128;
  const int t=threadIdx.x, lane=t&31, w=t>>5;
  const int gq=lane>>3, rr=lane&7;
  const __half* Qf=g_Qf+((size_t)bh*SS+m0)*HD;
  const __half* Kf=g_Kf+(size_t)bh*SS*HD;
  const __half* Vt=g_Tf+(size_t)bh*HD*SS;

  for(int i=t;i<1024;i+=256){
    int c4=i>>8, rh=i&255, row=rh>>1, hf=rh&1;
    cpa(sm+c4*4096+swz(row,hf), Qf+(size_t)row*HD+c4*16+hf*8);
  }
  asm volatile("cp.async.commit_group;":::"memory");
  asm volatile("cp.async.wait_group 0;":::"memory");
  __syncthreads();
  u32 qf[4][4];
  const u32 offQ=swz(w*16+(gq&1)*8+rr, gq>>1);
  #pragma unroll
  for(int c4=0;c4<4;c4++) ldmx4(qf[c4],sm+c4*4096+offQ);
  __syncthreads();

  u32 offB[4];
  #pragma unroll
  for(int p=0;p<4;p++) offB[p]=swz(p*16+(gq&1)*8+rr, gq>>1);

  auto fill=[&](int jj){
    const u32 sb=sm+(jj&1)*32768;
    const int n0=jj*128;
    for(int i=t;i<1024;i+=256){
      int c4=i>>8, kk=i&255, key=kk>>1, hf=kk&1;
      cpa(sb+c4*4096+swz(key,hf), Kf+(size_t)(n0+key)*HD+c4*16+hf*8);
    }
    for(int i=t;i<1024;i+=256){
      int g4=i>>7, hh=i&127, hd=hh>>1, hf=hh&1;
      cpa(sb+16384+g4*2048+swz(hd,hf), Vt+(size_t)hd*SS+n0+g4*16+hf*8);
    }
    asm volatile("cp.async.commit_group;":::"memory");
  };

  float ctx[32];
  #pragma unroll
  for(int i=0;i<32;i++) ctx[i]=0.f;
  float l0=0.f,l1=0.f;

  fill(0);
  for(int jj=0;jj<16;jj++){
    asm volatile("cp.async.wait_group 0;":::"memory");
    __syncthreads();
    if(jj+1<16) fill(jj+1);
    const u32 sb=sm+(jj&1)*32768;

    #pragma unroll
    for(int sub=0;sub<2;sub++){
      const u32 kof=sb+sub*2048;
      float s[32];
      #pragma unroll
      for(int i=0;i<32;i++) s[i]=0.f;
      #pragma unroll
      for(int c4=0;c4<4;c4++){
        u32 kb[4][4];
        #pragma unroll
        for(int p=0;p<4;p++) ldmx4(kb[p],kof+c4*4096+offB[p]);
        #pragma unroll
        for(int n=0;n<8;n++){
          float* cp=s+4*n; int p=n>>1,o=n&1;
          mmah(cp,qf[c4],kb[p][o],kb[p][2+o]);
        }
      }
      #pragma unroll
      for(int n=0;n<8;n++){
        s[4*n]=exp2f(s[4*n]);     s[4*n+1]=exp2f(s[4*n+1]);  l0+=s[4*n]+s[4*n+1];
        s[4*n+2]=exp2f(s[4*n+2]); s[4*n+3]=exp2f(s[4*n+3]);  l1+=s[4*n+2]+s[4*n+3];
      }
      u32 a_[4][4];
      #pragma unroll
      for(int g=0;g<4;g++){
        a_[g][0]=pkh(s[8*g+0],s[8*g+1]); a_[g][1]=pkh(s[8*g+2],s[8*g+3]);
        a_[g][2]=pkh(s[8*g+4],s[8*g+5]); a_[g][3]=pkh(s[8*g+6],s[8*g+7]);
      }
      #pragma unroll
      for(int g=0;g<4;g++){
        u32 vb[4][4];
        #pragma unroll
        for(int p=0;p<4;p++) ldmx4(vb[p],sb+16384+(sub*4+g)*2048+offB[p]);
        #pragma unroll
        for(int n=0;n<8;n++)
          mmah(ctx+4*n, a_[g], vb[n>>1][n&1], vb[n>>1][(n&1)+2]);
      }
      {
        int j=jj*2+sub;
        size_t po=((((size_t)(bh*16+qt)*32 + j)*8 + w)*4)*128 + (lane<<2);
        #pragma unroll
        for(int g=0;g<4;g++)
          asm volatile("st.global.cs.v4.u32 [%0],{%1,%2,%3,%4};"
            ::"l"(g_Pu+po+g*128),"r"(a_[g][0]),"r"(a_[g][1]),"r"(a_[g][2]),"r"(a_[g][3]):"memory");
      }
    }
  }
  l0+=__shfl_xor_sync(~0u,l0,1); l0+=__shfl_xor_sync(~0u,l0,2);
  l1+=__shfl_xor_sync(~0u,l1,1); l1+=__shfl_xor_sync(~0u,l1,2);

  float inv0=1.f/l0, inv1=1.f/l1;
  int r0=m0+w*16+(lane>>2), r1=r0+8;
  int b=bh>>4, h=bh&15;
  #pragma unroll
  for(int n=0;n<8;n++){
    u32 p0=pkh(ctx[4*n]*inv0, ctx[4*n+1]*inv0);
    u32 p1=pkh(ctx[4*n+2]*inv1, ctx[4*n+3]*inv1);
    int col=h*64+n*8+(lane&3)*2;
    *(u32*)(g_cf+((size_t)(b*SS+r0))*DD+col)=p0;
    *(u32*)(g_cf+((size_t)(b*SS+r1))*DD+col)=p1;
  }
  if((lane&3)==0){
    g_l[(size_t)bh*SS+r0]=l0;  g_l[(size_t)bh*SS+r1]=l1;
  }
}

__global__ __launch_bounds__(256) void k_avg(float* __restrict__ avg){
  extern __shared__ float buf[];   // [128][65]
  const int j=blockIdx.x, qt=blockIdx.y, b=blockIdx.z;
  const int t=threadIdx.x, lane=t&31, w=t>>5;
  const int q0=qt*128+w*16+(lane>>2);
  float acc[32];
  #pragma unroll
  for(int i=0;i<32;i++) acc[i]=0.f;

  for(int h=0;h<HH;h++){
    const int bh=b*HH+h;
    const float il0=1.f/__ldg(g_l+(size_t)bh*SS+q0);
    const float il1=1.f/__ldg(g_l+(size_t)bh*SS+q0+8);
    const size_t po=((((size_t)(bh*16+qt)*32 + j)*8 + w)*4)*128 + (lane<<2);
    #pragma unroll
    for(int g=0;g<4;g++){
      uint4 v;
      asm volatile("ld.global.cs.v4.u32 {%0,%1,%2,%3},[%4];"
        :"=r"(v.x),"=r"(v.y),"=r"(v.z),"=r"(v.w):"l"(g_Pu+po+g*128));
      float2 f0=__half22float2(*(__half2*)&v.x);
      float2 f1=__half22float2(*(__half2*)&v.y);
      float2 f2=__half22float2(*(__half2*)&v.z);
      float2 f3=__half22float2(*(__half2*)&v.w);
      acc[g*8+0]+=f0.x*il0; acc[g*8+1]+=f0.y*il0;
      acc[g*8+2]+=f1.x*il1; acc[g*8+3]+=f1.y*il1;
      acc[g*8+4]+=f2.x*il0; acc[g*8+5]+=f2.y*il0;
      acc[g*8+6]+=f3.x*il1; acc[g*8+7]+=f3.y*il1;
    }
  }
  const float sch=1.f/HH;
  const int rl=w*16+(lane>>2), cl=(lane&3)*2;
  #pragma unroll
  for(int g=0;g<4;g++){
    buf[rl*65+g*16+cl]      =acc[g*8+0]*sch;
    buf[rl*65+g*16+cl+1]    =acc[g*8+1]*sch;
    buf[(rl+8)*65+g*16+cl]  =acc[g*8+2]*sch;
    buf[(rl+8)*65+g*16+cl+1]=acc[g*8+3]*sch;
    buf[rl*65+g*16+8+cl]      =acc[g*8+4]*sch;
    buf[rl*65+g*16+8+cl+1]    =acc[g*8+5]*sch;
    buf[(rl+8)*65+g*16+8+cl]  =acc[g*8+6]*sch;
    buf[(rl+8)*65+g*16+8+cl+1]=acc[g*8+7]*sch;
  }
  __syncthreads();
  #pragma unroll
  for(int i=0;i<8;i++){
    int lin=t+i*256; int row=lin>>4, c4=(lin&15)*4;
    float4 o=make_float4(buf[row*65+c4],buf[row*65+c4+1],buf[row*65+c4+2],buf[row*65+c4+3]);
    *(float4*)(avg+((size_t)(b*SS+qt*128+row))*SS + j*64 + c4)=o;
  }
}

__global__ __launch_bounds__(256) void k_out(const float* __restrict__ bo,const float* __restrict__ x){
  int m0=blockIdx.y*128, n0=blockIdx.x*128;
  float c[64];
  gemm<128,128,2,4,3>(g_cf+(size_t)m0*DD, DD,
                      g_Wf+(size_t)3*DD*DD+(size_t)n0*DD, DD, DD/32, c);
  int lane=threadIdx.x&31, wid=threadIdx.x>>5, wm=wid>>2, wn=wid&3, rb=lane>>2, tg=lane&3;
  #pragma unroll
  for(int mt=0;mt<4;mt++)
    #pragma unroll
    for(int nt=0;nt<4;nt++){
      int col=n0+wn*32+nt*8+2*tg; const float* cc=c+(mt*4+nt)*4;
      float b0=__ldg(bo+col), b1=__ldg(bo+col+1);
      #pragma unroll
      for(int hf=0;hf<2;hf++){
        int m=m0+wm*64+mt*16+rb+hf*8;
        size_t off=(size_t)m*DD+col;
        *(float2*)(g_h+off)=make_float2(cc[2*hf]+b0+x[off], cc[2*hf+1]+b1+x[off+1]);
      }
    }
}

__global__ __launch_bounds__(256) void k_ln(const float* __restrict__ ln_g,const float* __restrict__ ln_b,
                                            float* __restrict__ out){
  int m=blockIdx.x, t=threadIdx.x;
  float4 v=((const float4*)(g_h+(size_t)m*DD))[t];
  float sum=(v.x+v.y)+(v.z+v.w);
  float sq=v.x*v.x+v.y*v.y+v.z*v.z+v.w*v.w;
  sum=bsum(sum); sq=bsum(sq);
  float mu=sum*(1.f/DD), var=sq*(1.f/DD)-mu*mu, rs=rsqrtf(var+1e-5f);
  float4 g=((const float4*)ln_g)[t], b=((const float4*)ln_b)[t];
  float4 o;
  o.x=(v.x-mu)*rs*g.x+b.x; o.y=(v.y-mu)*rs*g.y+b.y;
  o.z=(v.z-mu)*rs*g.z+b.z; o.w=(v.w-mu)*rs*g.w+b.w;
  ((float4*)(out+(size_t)m*DD))[t]=o;
}

extern "C" void kernel_launch(void* const* d_in, const int* in_sizes, int n_in,
                              void* d_out, int out_size)
{
  const float* x   =(const float*)d_in[0];
  const float* Wq  =(const float*)d_in[1];
  const float* bq  =(const float*)d_in[2];
  const float* Wk  =(const float*)d_in[3];
  const float* bk  =(const float*)d_in[4];
  const float* Wv  =(const float*)d_in[5];
  const float* bv  =(const float*)d_in[6];
  const float* Wo  =(const float*)d_in[7];
  const float* bo  =(const float*)d_in[8];
  const float* lng =(const float*)d_in[9];
  const float* lnb =(const float*)d_in[10];
  float* out=(float*)d_out;
  float* avg=out+(size_t)BB*SS*DD;

  cudaFuncSetAttribute(k_flash, cudaFuncAttributeMaxDynamicSharedMemorySize, 65536);

  cudaStream_t s2;
  cudaEvent_t e0,e1,e2,e3;
  cudaStreamCreateWithFlags(&s2,cudaStreamNonBlocking);
  cudaEventCreateWithFlags(&e0,cudaEventDisableTiming);
  cudaEventCreateWithFlags(&e1,cudaEventDisableTiming);
  cudaEventCreateWithFlags(&e2,cudaEventDisableTiming);
  cudaEventCreateWithFlags(&e3,cudaEventDisableTiming);

  cudaEventRecord(e0,0);
  cudaStreamWaitEvent(s2,e0,0);
  k_wt<<<dim3(32,32,4),256,0,s2>>>(Wq,Wk,Wv,Wo);
  k_cvt<<<4096,256>>>(x);
  cudaEventRecord(e1,s2);
  cudaStreamWaitEvent(0,e1,0);

  k_qkv<<<dim3(8,64,3),256,49152>>>(bq,bk,bv);
  k_flash<<<dim3(16,64),256,65536>>>();

  cudaEventRecord(e2,0);
  cudaStreamWaitEvent(s2,e2,0);
  k_avg<<<dim3(32,16,4),256,33280,s2>>>(avg);
  k_out<<<dim3(8,64),256,49152>>>(bo,x);
  k_ln<<<MM,256>>>(lng,lnb,out);
  cudaEventRecord(e3,s2);
  cudaStreamWaitEvent(0,e3,0);

  cudaEventDestroy(e0); cudaEventDestroy(e1);
  cudaEventDestroy(e2); cudaEventDestroy(e3);
  cudaStreamDestroy(s2);
}